// round 6
// baseline (speedup 1.0000x reference)
#include <cuda_runtime.h>
#include <math.h>

#define BB   64
#define TT   64
#define VB   32000
#define DD   512
#define NDIM 256
#define NNT  512
#define CAPN 130
#define ZD   1280
#define LW   1536

// output offsets (floats) in d_out, reference return order:
// logits (B,T,V), pushes (B,T,2), raw_codes (B,T,2,ND), m_new (NNT,ND), n_new (NNT)
#define O_PUSH   131072000ULL
#define O_CODES  131080192ULL
#define O_M      133177344ULL
#define O_N      133308416ULL

// ---------------- device scratch (static; no allocation) ----------------
__device__ __align__(16) float g_z[BB * ZD];          // next-step cell input [emb|top|h_state]
__device__ __align__(16) float g_lin[BB * LW];        // raw z@[Wtok|Wnt|Wst] (pre-tanh)
__device__ __align__(16) float g_clin[BB * 2 * NDIM]; // raw codes
__device__ __align__(16) float g_h_all[(size_t)TT * BB * DD]; // tanh'd h_t, (t,b,d)
__device__ __align__(16) float g_stack[BB * CAPN * NDIM];
__device__ int   g_ptr[BB];
__device__ int   g_stepmask[BB];
__device__ __align__(16) float g_accm[NNT * NDIM];
__device__ float g_accn[NNT];
__device__ float g_codesq[NNT];
__device__ int   g_xi64;   // 1 if token buffer is int64, 0 if int32

union U2 { unsigned long long u; float2 f; };

__device__ __forceinline__ unsigned long long ffma2(unsigned long long a,
                                                    unsigned long long b,
                                                    unsigned long long c) {
    unsigned long long d;
    asm("fma.rn.f32x2 %0, %1, %2, %3;" : "=l"(d) : "l"(a), "l"(b), "l"(c));
    return d;
}

__device__ __forceinline__ int get_tok(const void* x, int i) {
    if (g_xi64) return (int)((const long long*)x)[i];
    return ((const int*)x)[i];
}

// ---------------- token dtype detection ----------------
// int64 tokens: every 8-byte word has hi==0 and value < VOCAB.
// int32 tokens: 8-byte words interleave two tokens -> hi word nonzero w.h.p.
__global__ void k_detect(const void* __restrict__ x) {
    if (threadIdx.x == 0 && blockIdx.x == 0) {
        const unsigned long long* p = (const unsigned long long*)x;
        int i64 = 1;
        for (int i = 0; i < 64; i++) {
            unsigned long long v = p[i];
            if ((v >> 32) != 0ULL || v >= (unsigned long long)VB) { i64 = 0; break; }
        }
        g_xi64 = i64;
    }
}

// ---------------- init: zero state, code_sq, z(t=0) ----------------
__global__ void k_init(const void* __restrict__ x, const int* __restrict__ xm,
                       const float* __restrict__ emb, const float* __restrict__ cb) {
    int gid = blockIdx.x * blockDim.x + threadIdx.x;
    int stride = gridDim.x * blockDim.x;
    for (int i = gid; i < BB * CAPN * NDIM; i += stride) g_stack[i] = 0.f;
    for (int i = gid; i < NNT * NDIM; i += stride) g_accm[i] = 0.f;
    for (int i = gid; i < BB * LW; i += stride) g_lin[i] = 0.f;
    for (int i = gid; i < BB * 2 * NDIM; i += stride) g_clin[i] = 0.f;
    for (int i = gid; i < NNT; i += stride) {
        g_accn[i] = 0.f;
        const float* e = cb + (size_t)i * NDIM;
        float s = 0.f;
        for (int d = 0; d < NDIM; d++) s = fmaf(e[d], e[d], s);
        g_codesq[i] = s;
    }
    for (int i = gid; i < BB; i += stride) {
        // ptr0=1, pop at t=0: top_mask=1, top=0 (buf zero), ptr->0
        g_ptr[i] = 0;
        g_stepmask[i] = xm[i * TT];
    }
    for (int i = gid; i < BB * ZD; i += stride) {
        int b = i / ZD, j = i - b * ZD;
        float v = 0.f;
        if (j < DD) { int tok = get_tok(x, b * TT); v = emb[(size_t)tok * DD + j]; }
        g_z[i] = v;  // top and h_state start at 0
    }
}

// ---------------- cell GEMM: g_lin += z(64x1280) @ [Wtok|Wnt|Wst] (1280x1536) ----------------
// grid (48 n-tiles of 32, 4 k-chunks of 320), 128 threads; per-thread 8M x 2N
__global__ void __launch_bounds__(128) k_cell(const float* __restrict__ Wtok,
                                              const float* __restrict__ Wnt,
                                              const float* __restrict__ Wst) {
    __shared__ __align__(16) float2 As2[32 * 64];
    __shared__ __align__(16) float  Bs[32 * 32];
    const int tid = threadIdx.x;
    const int tx = tid & 15, ty = tid >> 4;
    const int n0 = blockIdx.x * 32;
    const int kbase = blockIdx.y * 320;
    const int mat = n0 >> 9;
    const int ncol = n0 & 511;
    const float* W = (mat == 0) ? Wtok : ((mat == 1) ? Wnt : Wst);
    unsigned long long acc[8];
#pragma unroll
    for (int j = 0; j < 8; j++) acc[j] = 0ULL;

    for (int it = 0; it < 10; it++) {
        int k0 = kbase + it * 32;
#pragma unroll
        for (int i = 0; i < 4; i++) {               // A: 64x32, duplicated float2
            int idx = tid + i * 128;
            int m = idx >> 3, q = idx & 7;
            float4 v = *(const float4*)&g_z[m * ZD + k0 + q * 4];
            As2[(q * 4 + 0) * 64 + m] = make_float2(v.x, v.x);
            As2[(q * 4 + 1) * 64 + m] = make_float2(v.y, v.y);
            As2[(q * 4 + 2) * 64 + m] = make_float2(v.z, v.z);
            As2[(q * 4 + 3) * 64 + m] = make_float2(v.w, v.w);
        }
#pragma unroll
        for (int i = 0; i < 2; i++) {               // B: 32x32
            int idx = tid + i * 128;
            int kk = idx >> 3, q = idx & 7;
            float4 v = *(const float4*)&W[(size_t)(k0 + kk) * DD + ncol + q * 4];
            *(float4*)&Bs[kk * 32 + q * 4] = v;
        }
        __syncthreads();
#pragma unroll 4
        for (int kk = 0; kk < 32; kk++) {
            const ulonglong2* ap = (const ulonglong2*)&As2[kk * 64 + 8 * ty];
            ulonglong2 A01 = ap[0], A23 = ap[1], A45 = ap[2], A67 = ap[3];
            unsigned long long av[8] = {A01.x, A01.y, A23.x, A23.y, A45.x, A45.y, A67.x, A67.y};
            unsigned long long bb = *(const unsigned long long*)&Bs[kk * 32 + 2 * tx];
#pragma unroll
            for (int jm = 0; jm < 8; jm++) acc[jm] = ffma2(av[jm], bb, acc[jm]);
        }
        __syncthreads();
    }
#pragma unroll
    for (int j = 0; j < 8; j++) {
        U2 u; u.u = acc[j];
        int m = 8 * ty + j;
        atomicAdd(&g_lin[m * LW + n0 + 2 * tx], u.f.x);
        atomicAdd(&g_lin[m * LW + n0 + 2 * tx + 1], u.f.y);
    }
}

// ---------------- codes GEMM: g_clin += [tanh(h_ntt)|tanh(h_t)](64x1024) @ W_code ----------------
// grid (16 n-tiles of 32, 4 k-chunks of 256), 128 threads
__global__ void __launch_bounds__(128) k_codes(const float* __restrict__ Wc) {
    __shared__ __align__(16) float2 As2[32 * 64];
    __shared__ __align__(16) float  Bs[32 * 32];
    const int tid = threadIdx.x;
    const int tx = tid & 15, ty = tid >> 4;
    const int n0 = blockIdx.x * 32;
    const int kbase = blockIdx.y * 256;
    unsigned long long acc[8];
#pragma unroll
    for (int j = 0; j < 8; j++) acc[j] = 0ULL;

    for (int it = 0; it < 8; it++) {
        int k0 = kbase + it * 32;
        int cbase = (k0 < 512) ? (512 + k0) : (k0 - 512);  // [h_ntt | h_t] column map
#pragma unroll
        for (int i = 0; i < 4; i++) {
            int idx = tid + i * 128;
            int m = idx >> 3, q = idx & 7;
            float4 v = *(const float4*)&g_lin[m * LW + cbase + q * 4];
            v.x = tanhf(v.x); v.y = tanhf(v.y); v.z = tanhf(v.z); v.w = tanhf(v.w);
            As2[(q * 4 + 0) * 64 + m] = make_float2(v.x, v.x);
            As2[(q * 4 + 1) * 64 + m] = make_float2(v.y, v.y);
            As2[(q * 4 + 2) * 64 + m] = make_float2(v.z, v.z);
            As2[(q * 4 + 3) * 64 + m] = make_float2(v.w, v.w);
        }
#pragma unroll
        for (int i = 0; i < 2; i++) {
            int idx = tid + i * 128;
            int kk = idx >> 3, q = idx & 7;
            float4 v = *(const float4*)&Wc[(size_t)(k0 + kk) * 512 + n0 + q * 4];
            *(float4*)&Bs[kk * 32 + q * 4] = v;
        }
        __syncthreads();
#pragma unroll 4
        for (int kk = 0; kk < 32; kk++) {
            const ulonglong2* ap = (const ulonglong2*)&As2[kk * 64 + 8 * ty];
            ulonglong2 A01 = ap[0], A23 = ap[1], A45 = ap[2], A67 = ap[3];
            unsigned long long av[8] = {A01.x, A01.y, A23.x, A23.y, A45.x, A45.y, A67.x, A67.y};
            unsigned long long bb = *(const unsigned long long*)&Bs[kk * 32 + 2 * tx];
#pragma unroll
            for (int jm = 0; jm < 8; jm++) acc[jm] = ffma2(av[jm], bb, acc[jm]);
        }
        __syncthreads();
    }
#pragma unroll
    for (int j = 0; j < 8; j++) {
        U2 u; u.u = acc[j];
        int m = 8 * ty + j;
        atomicAdd(&g_clin[m * 512 + n0 + 2 * tx], u.f.x);
        atomicAdd(&g_clin[m * 512 + n0 + 2 * tx + 1], u.f.y);
    }
}

// ---------------- per-batch: quantize, stack, EMA, outputs, next z ----------------
__global__ void __launch_bounds__(256) k_quant(int t, int last,
        const void* __restrict__ x, const int* __restrict__ xm,
        const float* __restrict__ emb, const float* __restrict__ cb,
        float* __restrict__ out) {
    __shared__ float c0s[256], c1s[256];
    __shared__ float rv0[256], rv1[256];
    __shared__ int   ri0[256], ri1[256];
    __shared__ float s_cc[2];
    __shared__ int   s_info[6];
    const int b = blockIdx.x, tid = threadIdx.x;

    c0s[tid] = g_clin[b * 512 + tid];
    c1s[tid] = g_clin[b * 512 + 256 + tid];
    __syncthreads();

    // |code|^2 (reference includes it in the distance composition)
    rv0[tid] = c0s[tid] * c0s[tid];
    rv1[tid] = c1s[tid] * c1s[tid];
    __syncthreads();
    for (int s = 128; s > 0; s >>= 1) {
        if (tid < s) { rv0[tid] += rv0[tid + s]; rv1[tid] += rv1[tid + s]; }
        __syncthreads();
    }
    if (tid == 0) { s_cc[0] = rv0[0]; s_cc[1] = rv1[0]; }
    __syncthreads();
    const float cc0 = s_cc[0], cc1 = s_cc[1];

    // nearest codebook entry: argmin over n of (cc - 2*dot) + sq[n]
    float bv0 = 3.4e38f, bv1 = 3.4e38f;
    int   bi0 = 0,       bi1 = 0;
#pragma unroll
    for (int r = 0; r < 2; r++) {
        int n = tid + r * 256;
        const float4* e = (const float4*)&cb[(size_t)n * NDIM];
        float d0 = 0.f, d1 = 0.f;
#pragma unroll 8
        for (int q = 0; q < 64; q++) {
            float4 v = e[q];
            float4 a = *(const float4*)&c0s[q * 4];
            float4 c = *(const float4*)&c1s[q * 4];
            d0 += v.x * a.x + v.y * a.y + v.z * a.z + v.w * a.w;
            d1 += v.x * c.x + v.y * c.y + v.z * c.z + v.w * c.w;
        }
        float s = g_codesq[n];
        float dist0 = (cc0 - 2.f * d0) + s;
        float dist1 = (cc1 - 2.f * d1) + s;
        if (dist0 < bv0) { bv0 = dist0; bi0 = n; }
        if (dist1 < bv1) { bv1 = dist1; bi1 = n; }
    }
    rv0[tid] = bv0; ri0[tid] = bi0; rv1[tid] = bv1; ri1[tid] = bi1;
    __syncthreads();
    for (int s = 128; s > 0; s >>= 1) {
        if (tid < s) {
            float v = rv0[tid + s]; int i = ri0[tid + s];
            if (v < rv0[tid] || (v == rv0[tid] && i < ri0[tid])) { rv0[tid] = v; ri0[tid] = i; }
            v = rv1[tid + s]; i = ri1[tid + s];
            if (v < rv1[tid] || (v == rv1[tid] && i < ri1[tid])) { rv1[tid] = v; ri1[tid] = i; }
        }
        __syncthreads();
    }
    if (tid == 0) {
        int q0 = ri0[0], q1 = ri1[0];
        int sm = g_stepmask[b];
        s_info[0] = q0; s_info[1] = q1;
        s_info[2] = q0 * sm; s_info[3] = q1 * sm;
        s_info[4] = g_ptr[b]; s_info[5] = sm;
        out[O_PUSH + (size_t)(b * TT + t) * 2 + 0] = (float)(q0 * sm);
        out[O_PUSH + (size_t)(b * TT + t) * 2 + 1] = (float)(q1 * sm);
    }
    __syncthreads();
    const int q0 = s_info[0], q1 = s_info[1];
    const int pm0 = s_info[2], pm1 = s_info[3];
    const int ptr = s_info[4], sm = s_info[5];

    // stack pushes (reference push semantics; capacity never reached with T=64)
    int w0 = (ptr < CAPN - 1) ? ptr : (CAPN - 1);
    int p1 = ptr + (pm0 != 0);
    int w1 = (p1 < CAPN - 1) ? p1 : (CAPN - 1);
    int pafter = p1 + (pm1 != 0);
    if (pm0) g_stack[(b * CAPN + w0) * NDIM + tid] = cb[(size_t)q0 * NDIM + tid];
    if (pm1) g_stack[(b * CAPN + w1) * NDIM + tid] = cb[(size_t)q1 * NDIM + tid];

    // EMA accumulators (raw codes, masked by step_mask)
    if (sm) {
        float f = (float)sm;
        atomicAdd(&g_accm[q0 * NDIM + tid], f * c0s[tid]);
        atomicAdd(&g_accm[q1 * NDIM + tid], f * c1s[tid]);
        if (tid == 0) { atomicAdd(&g_accn[q0], f); atomicAdd(&g_accn[q1], f); }
    }

    // raw codes output
    size_t co = O_CODES + (size_t)((b * TT + t) * 2) * NDIM;
    out[co + tid]        = c0s[tid];
    out[co + NDIM + tid] = c1s[tid];

    // stash tanh'd h_t for the deferred logits GEMM
    for (int j = tid; j < DD; j += 256)
        g_h_all[((size_t)t * BB + b) * DD + j] = tanhf(g_lin[b * LW + j]);

    __syncthreads();  // pushes visible before pop

    if (!last) {
        int tm = pafter > 0;
        int ti = tm ? (pafter - 1) : 0;
        float top = tm ? g_stack[(b * CAPN + ti) * NDIM + tid] : 0.f;
        g_z[b * ZD + DD + tid] = top;
        int tok = get_tok(x, b * TT + t + 1);
        for (int j = tid; j < DD; j += 256) g_z[b * ZD + j] = emb[(size_t)tok * DD + j];
        for (int j = tid; j < DD; j += 256) g_z[b * ZD + DD + NDIM + j] = g_lin[b * LW + 1024 + j];
        if (tid == 0) {
            g_ptr[b] = pafter - tm;
            g_stepmask[b] = xm[b * TT + t + 1] * tm;
        }
    }
    __syncthreads();  // all g_lin/g_clin reads done before zeroing

    for (int j = tid; j < LW; j += 256) g_lin[b * LW + j] = 0.f;
    g_clin[b * 512 + tid] = 0.f;
    g_clin[b * 512 + 256 + tid] = 0.f;
}

// ---------------- logits GEMM: H(4096x512) @ W_pred(512x32000) ----------------
// grid (250 n-tiles of 128, 64 m-tiles of 64), 128 threads; per-thread 8M x 8N, FFMA2
__global__ void __launch_bounds__(128) k_logits(const float* __restrict__ Wp,
                                                float* __restrict__ out) {
    __shared__ __align__(16) float2 As2[32 * 64];
    __shared__ __align__(16) float  Bs[32 * 128];
    const int tid = threadIdx.x;
    const int tx = tid & 15, ty = tid >> 4;
    const int n0 = blockIdx.x * 128;
    const int m0 = blockIdx.y * 64;
    unsigned long long acc[8][4];
#pragma unroll
    for (int i = 0; i < 8; i++)
#pragma unroll
        for (int j = 0; j < 4; j++) acc[i][j] = 0ULL;

    for (int it = 0; it < 16; it++) {
        int k0 = it * 32;
#pragma unroll
        for (int i = 0; i < 4; i++) {               // A: 64x32 from g_h_all
            int idx = tid + i * 128;
            int m = idx >> 3, q = idx & 7;
            float4 v = *(const float4*)&g_h_all[(size_t)(m0 + m) * DD + k0 + q * 4];
            As2[(q * 4 + 0) * 64 + m] = make_float2(v.x, v.x);
            As2[(q * 4 + 1) * 64 + m] = make_float2(v.y, v.y);
            As2[(q * 4 + 2) * 64 + m] = make_float2(v.z, v.z);
            As2[(q * 4 + 3) * 64 + m] = make_float2(v.w, v.w);
        }
#pragma unroll
        for (int i = 0; i < 8; i++) {               // B: 32x128 from W_pred
            int idx = tid + i * 128;
            int kk = idx >> 5, q = idx & 31;
            float4 v = *(const float4*)&Wp[(size_t)(k0 + kk) * VB + n0 + q * 4];
            *(float4*)&Bs[kk * 128 + q * 4] = v;
        }
        __syncthreads();
#pragma unroll 2
        for (int kk = 0; kk < 32; kk++) {
            const ulonglong2* ap = (const ulonglong2*)&As2[kk * 64 + 8 * ty];
            ulonglong2 A01 = ap[0], A23 = ap[1], A45 = ap[2], A67 = ap[3];
            unsigned long long av[8] = {A01.x, A01.y, A23.x, A23.y, A45.x, A45.y, A67.x, A67.y};
            const ulonglong2* bp = (const ulonglong2*)&Bs[kk * 128 + 8 * tx];
            ulonglong2 B01 = bp[0], B23 = bp[1];
            unsigned long long bv[4] = {B01.x, B01.y, B23.x, B23.y};
#pragma unroll
            for (int jm = 0; jm < 8; jm++)
#pragma unroll
                for (int jn = 0; jn < 4; jn++)
                    acc[jm][jn] = ffma2(av[jm], bv[jn], acc[jm][jn]);
        }
        __syncthreads();
    }
#pragma unroll
    for (int j = 0; j < 8; j++) {
        int m = m0 + 8 * ty + j;            // m = t*64 + b
        int row = (m & 63) * TT + (m >> 6); // out row = b*T + t
        size_t base = (size_t)row * VB + n0 + 8 * tx;
        U2 u0, u1, u2, u3;
        u0.u = acc[j][0]; u1.u = acc[j][1]; u2.u = acc[j][2]; u3.u = acc[j][3];
        *(float4*)&out[base]     = make_float4(u0.f.x, u0.f.y, u1.f.x, u1.f.y);
        *(float4*)&out[base + 4] = make_float4(u2.f.x, u2.f.y, u3.f.x, u3.f.y);
    }
}

// ---------------- EMA finalize ----------------
__global__ void k_ema(const float* __restrict__ macc, const float* __restrict__ nacc,
                      float* __restrict__ out) {
    int gid = blockIdx.x * blockDim.x + threadIdx.x;
    int stride = gridDim.x * blockDim.x;
    for (int i = gid; i < NNT * NDIM; i += stride)
        out[O_M + i] = 0.99f * macc[i] + 0.01f * g_accm[i];
    for (int i = gid; i < NNT; i += stride)
        out[O_N + i] = 0.99f * nacc[i] + 0.01f * g_accn[i];
}

extern "C" void kernel_launch(void* const* d_in, const int* in_sizes, int n_in,
                              void* d_out, int out_size) {
    const void*  x       = d_in[0];
    const int*   xm      = (const int*)d_in[1];
    const float* emb     = (const float*)d_in[2];
    const float* cb      = (const float*)d_in[3];
    const float* macc    = (const float*)d_in[4];
    const float* nacc    = (const float*)d_in[5];
    const float* Wtok    = (const float*)d_in[6];
    const float* Wnt     = (const float*)d_in[7];
    const float* Wst     = (const float*)d_in[8];
    const float* Wc      = (const float*)d_in[9];
    const float* Wp      = (const float*)d_in[10];
    float* out = (float*)d_out;

    k_detect<<<1, 32>>>(x);
    k_init<<<512, 256>>>(x, xm, emb, cb);
    for (int t = 0; t < TT; t++) {
        k_cell<<<dim3(48, 4), 128>>>(Wtok, Wnt, Wst);
        k_codes<<<dim3(16, 4), 128>>>(Wc);
        k_quant<<<64, 256>>>(t, (t == TT - 1) ? 1 : 0, x, xm, emb, cb, out);
    }
    k_logits<<<dim3(250, 64), 128>>>(Wp, out);
    k_ema<<<256, 256>>>(macc, nacc, out);
}